// round 5
// baseline (speedup 1.0000x reference)
#include <cuda_runtime.h>
#include <cuda_bf16.h>
#include <cstdint>

#define DIN   128
#define DOUT  128
#define MAXN  100000
#define BN_EPS 1e-5f

// Padded bf16 tile: 128 rows x 136 bf16 (272 B rows, 16B-aligned, conflict-free ldmatrix)
#define LDA_B    272
#define TILEA    (128 * LDA_B)          // 34816 B per operand tile
#define GEMM_DYN_SMEM (4 * TILEA + 1024)

// Scratch (allocation-free rule: __device__ globals)
__device__ float    g_hop1[(size_t)MAXN * DIN];
__device__ int      g_rowptr[MAXN + 1];
// [0..255]=colsum, [256..511]=colsumsq, [512..767]=scale, [768..1023]=shift
__device__ float    g_stats[1024];
// Dense bf16 weights, [n][k] (K-major for col-major B operand):
// per weight: hi[128*64 u32] then lo[128*64 u32]; weight w at offset w*16384
__device__ uint32_t g_wbf16[2 * 16384];

// ---------------------------------------------------------------------------
__device__ __forceinline__ uint32_t smem_u32(const void* p) {
    uint32_t a;
    asm("{ .reg .u64 t; cvta.to.shared.u64 t, %1; cvt.u32.u64 %0, t; }"
        : "=r"(a) : "l"(p));
    return a;
}
__device__ __forceinline__ void bf16_split(float x, uint32_t& hi, uint32_t& lo) {
    __nv_bfloat16 h = __float2bfloat16_rn(x);
    __nv_bfloat16 l = __float2bfloat16_rn(x - __bfloat162float(h));
    hi = (uint32_t)__bfloat16_as_ushort(h);
    lo = (uint32_t)__bfloat16_as_ushort(l);
}
__device__ __forceinline__ void ldsm4(uint32_t* r, uint32_t addr) {
    asm volatile("ldmatrix.sync.aligned.m8n8.x4.shared.b16 {%0,%1,%2,%3}, [%4];"
                 : "=r"(r[0]), "=r"(r[1]), "=r"(r[2]), "=r"(r[3]) : "r"(addr));
}
__device__ __forceinline__ void mma_bf16(float* d, const uint32_t* a,
                                         const uint32_t* b) {
    asm volatile(
        "mma.sync.aligned.m16n8k16.row.col.f32.bf16.bf16.f32 "
        "{%0,%1,%2,%3}, {%4,%5,%6,%7}, {%8,%9}, {%0,%1,%2,%3};"
        : "+f"(d[0]), "+f"(d[1]), "+f"(d[2]), "+f"(d[3])
        : "r"(a[0]), "r"(a[1]), "r"(a[2]), "r"(a[3]), "r"(b[0]), "r"(b[1]));
}

// ---------------------------------------------------------------------------
__global__ void zero_stats_kernel() {
    g_stats[threadIdx.x] = 0.0f;   // 512 threads
}

// adj_rows is sorted; scatter row boundaries into CSR row_ptr.
__global__ void build_rowptr_kernel(const int* __restrict__ rows, int E, int N) {
    int e = blockIdx.x * blockDim.x + threadIdx.x;
    if (e >= E) return;
    int r = rows[e];
    int prev = (e == 0) ? -1 : rows[e - 1];
    for (int rr = prev + 1; rr <= r; rr++) g_rowptr[rr] = e;
    if (e == E - 1) {
        for (int rr = r + 1; rr <= N; rr++) g_rowptr[rr] = E;
    }
}

// One warp per node, lane owns a float4 (4 dims), 4-edge unroll for MLP.
__global__ void spmm_kernel(const float* __restrict__ feat,
                            const float* __restrict__ vals,
                            const int*   __restrict__ cols,
                            int N) {
    int warp = (blockIdx.x * blockDim.x + threadIdx.x) >> 5;
    int lane = threadIdx.x & 31;
    if (warp >= N) return;
    int s = g_rowptr[warp];
    int e = g_rowptr[warp + 1];
    float4 acc0 = make_float4(0.f, 0.f, 0.f, 0.f);
    float4 acc1 = make_float4(0.f, 0.f, 0.f, 0.f);
    int t = s;
    for (; t + 3 < e; t += 4) {
        float v0 = __ldg(&vals[t]),     v1 = __ldg(&vals[t + 1]);
        float v2 = __ldg(&vals[t + 2]), v3 = __ldg(&vals[t + 3]);
        int c0 = __ldg(&cols[t]),     c1 = __ldg(&cols[t + 1]);
        int c2 = __ldg(&cols[t + 2]), c3 = __ldg(&cols[t + 3]);
        float4 x0 = __ldg(&((const float4*)&feat[(size_t)c0 * DIN])[lane]);
        float4 x1 = __ldg(&((const float4*)&feat[(size_t)c1 * DIN])[lane]);
        float4 x2 = __ldg(&((const float4*)&feat[(size_t)c2 * DIN])[lane]);
        float4 x3 = __ldg(&((const float4*)&feat[(size_t)c3 * DIN])[lane]);
        acc0.x = fmaf(v0, x0.x, acc0.x); acc0.y = fmaf(v0, x0.y, acc0.y);
        acc0.z = fmaf(v0, x0.z, acc0.z); acc0.w = fmaf(v0, x0.w, acc0.w);
        acc1.x = fmaf(v1, x1.x, acc1.x); acc1.y = fmaf(v1, x1.y, acc1.y);
        acc1.z = fmaf(v1, x1.z, acc1.z); acc1.w = fmaf(v1, x1.w, acc1.w);
        acc0.x = fmaf(v2, x2.x, acc0.x); acc0.y = fmaf(v2, x2.y, acc0.y);
        acc0.z = fmaf(v2, x2.z, acc0.z); acc0.w = fmaf(v2, x2.w, acc0.w);
        acc1.x = fmaf(v3, x3.x, acc1.x); acc1.y = fmaf(v3, x3.y, acc1.y);
        acc1.z = fmaf(v3, x3.z, acc1.z); acc1.w = fmaf(v3, x3.w, acc1.w);
    }
    for (; t < e; t++) {
        float v0 = __ldg(&vals[t]);
        int   c0 = __ldg(&cols[t]);
        float4 x0 = __ldg(&((const float4*)&feat[(size_t)c0 * DIN])[lane]);
        acc0.x = fmaf(v0, x0.x, acc0.x); acc0.y = fmaf(v0, x0.y, acc0.y);
        acc0.z = fmaf(v0, x0.z, acc0.z); acc0.w = fmaf(v0, x0.w, acc0.w);
    }
    acc0.x += acc1.x; acc0.y += acc1.y; acc0.z += acc1.z; acc0.w += acc1.w;
    ((float4*)&g_hop1[(size_t)warp * DIN])[lane] = acc0;
}

// ---------------------------------------------------------------------------
// One-time W prep: W[k][n] fp32 -> [n][k] bf16 hi/lo (dense, K-major).
__global__ void prep_w_kernel(const float* __restrict__ W0,
                              const float* __restrict__ W1) {
    int w = blockIdx.x;
    const float* W = w ? W1 : W0;
    uint32_t* hi = &g_wbf16[w * 16384];
    uint32_t* lo = hi + 8192;
    // idx: n (128) x 16 chunks of 8 k-values
    for (int idx = threadIdx.x; idx < 2048; idx += blockDim.x) {
        int n  = idx >> 4;
        int k0 = (idx & 15) * 8;
        uint32_t hp[4], lp[4];
#pragma unroll
        for (int j = 0; j < 4; j++) {
            float x0 = __ldg(&W[(size_t)(k0 + 2 * j) * DOUT + n]);
            float x1 = __ldg(&W[(size_t)(k0 + 2 * j + 1) * DOUT + n]);
            uint32_t h0, l0, h1, l1;
            bf16_split(x0, h0, l0);
            bf16_split(x1, h1, l1);
            hp[j] = h0 | (h1 << 16);
            lp[j] = l0 | (l1 << 16);
        }
        int o = n * 64 + k0 / 2;            // u32 offset, 16B aligned
        *(uint4*)&hi[o] = make_uint4(hp[0], hp[1], hp[2], hp[3]);
        *(uint4*)&lo[o] = make_uint4(lp[0], lp[1], lp[2], lp[3]);
    }
}

// ---------------------------------------------------------------------------
// Warp-MMA GEMM: out[:, col_off..+127] = relu(X @ W) + bias, plus BN stats.
// Split-bf16: D = Ah@Bh + Ah@Bl + Al@Bh (fp32 accumulators).
// 8 warps (2 M x 4 N), warp tile 64x32, mma.sync m16n8k16 bf16.
// SMEM: A_hi | A_lo | B_hi | B_lo (each 128 x 272B padded). Epilogue stage
// (fp32, stride 132) reuses the tile memory.
__global__ __launch_bounds__(256, 1)
void gemm_mma_kernel(const float* __restrict__ X,
                     const uint4* __restrict__ wt,   // hi(2048 uint4)+lo(2048)
                     const float* __restrict__ bias,
                     float* __restrict__ out,
                     int N, int col_off) {
    extern __shared__ char dyn_smem[];
    char*  tiles = (char*)(((uintptr_t)dyn_smem + 1023) & ~(uintptr_t)1023);
    float* stage = (float*)tiles;
    uint32_t tiles_u = smem_u32(tiles);

    int tid  = threadIdx.x;
    int lane = tid & 31;
    int warp = tid >> 5;
    int wm = warp >> 2;                  // 0..1 -> M offset wm*64
    int wn = warp & 3;                   // 0..3 -> N offset wn*32
    int m0 = blockIdx.x * 128;

    // --- load + convert A tile: thread = (row, 64-col half) ----------------
    {
        int r    = tid >> 1;
        int half = tid & 1;
        int gr   = m0 + r;
        char* ahit = tiles;
        char* alot = tiles + TILEA;
        const float4* xrow = (gr < N)
            ? (const float4*)&X[(size_t)gr * DIN + half * 64] : nullptr;
#pragma unroll 4
        for (int q = 0; q < 16; q++) {
            float4 v = xrow ? __ldg(&xrow[q]) : make_float4(0.f, 0.f, 0.f, 0.f);
            uint32_t h0, l0, h1, l1, h2, l2, h3, l3;
            bf16_split(v.x, h0, l0); bf16_split(v.y, h1, l1);
            bf16_split(v.z, h2, l2); bf16_split(v.w, h3, l3);
            uint32_t off = (uint32_t)r * LDA_B + half * 128 + q * 8;
            *(uint2*)(ahit + off) = make_uint2(h0 | (h1 << 16), h2 | (h3 << 16));
            *(uint2*)(alot + off) = make_uint2(l0 | (l1 << 16), l2 | (l3 << 16));
        }
    }
    // --- copy pre-converted W into padded SMEM layout ----------------------
    {
        char* bbase = tiles + 2 * TILEA;   // B_hi then B_lo
        for (int i = tid; i < 4096; i += 256) {
            uint4 v  = __ldg(&wt[i]);
            int  arr = i >> 11;            // 0: hi, 1: lo
            int  ai  = i & 2047;
            int  n   = ai >> 4;
            int  q   = ai & 15;
            *(uint4*)(bbase + arr * TILEA + n * LDA_B + q * 16) = v;
        }
    }
    __syncthreads();

    // --- ldmatrix base offsets ---------------------------------------------
    uint32_t Ahi_u = tiles_u;
    uint32_t Alo_u = tiles_u + TILEA;
    uint32_t Bhi_u = tiles_u + 2 * TILEA;
    uint32_t Blo_u = tiles_u + 3 * TILEA;
    uint32_t a_off = (uint32_t)(wm * 64 + (lane & 15)) * LDA_B + (lane >> 4) * 16;
    uint32_t b_off = (uint32_t)(wn * 32 + (lane & 7) + ((lane >> 4) & 1) * 8) * LDA_B
                   + ((lane >> 3) & 1) * 16;

    float acc[4][4][4];
#pragma unroll
    for (int mi = 0; mi < 4; mi++)
#pragma unroll
        for (int ni = 0; ni < 4; ni++)
#pragma unroll
            for (int j = 0; j < 4; j++) acc[mi][ni][j] = 0.f;

#pragma unroll
    for (int k = 0; k < 8; k++) {
        uint32_t kb = k * 32;              // 16 bf16 per step
        uint32_t ah[4][4], al[4][4];
#pragma unroll
        for (int mi = 0; mi < 4; mi++) {
            uint32_t o = a_off + mi * 16 * LDA_B + kb;
            ldsm4(ah[mi], Ahi_u + o);
            ldsm4(al[mi], Alo_u + o);
        }
        uint32_t bh[4][2], bl[4][2];
#pragma unroll
        for (int p = 0; p < 2; p++) {
            uint32_t o = b_off + p * 16 * LDA_B + kb;
            uint32_t t[4];
            ldsm4(t, Bhi_u + o);
            bh[p * 2][0] = t[0]; bh[p * 2][1] = t[1];
            bh[p * 2 + 1][0] = t[2]; bh[p * 2 + 1][1] = t[3];
            ldsm4(t, Blo_u + o);
            bl[p * 2][0] = t[0]; bl[p * 2][1] = t[1];
            bl[p * 2 + 1][0] = t[2]; bl[p * 2 + 1][1] = t[3];
        }
#pragma unroll
        for (int mi = 0; mi < 4; mi++)
#pragma unroll
            for (int ni = 0; ni < 4; ni++) {
                mma_bf16(acc[mi][ni], ah[mi], bh[ni]);
                mma_bf16(acc[mi][ni], ah[mi], bl[ni]);
                mma_bf16(acc[mi][ni], al[mi], bh[ni]);
            }
    }
    __syncthreads();   // done reading operand tiles; reuse as stage

    // --- epilogue: relu + bias -> stage (zeros for invalid rows) -----------
#pragma unroll
    for (int mi = 0; mi < 4; mi++) {
        int r0 = wm * 64 + mi * 16 + (lane >> 2);
        bool v0 = (m0 + r0) < N;
        bool v1 = (m0 + r0 + 8) < N;
#pragma unroll
        for (int ni = 0; ni < 4; ni++) {
            int c = wn * 32 + ni * 8 + (lane & 3) * 2;
            float b0 = __ldg(&bias[c]);
            float b1 = __ldg(&bias[c + 1]);
            float* s0 = &stage[r0 * 132 + c];
            float* s1 = &stage[(r0 + 8) * 132 + c];
            s0[0] = v0 ? fmaxf(acc[mi][ni][0], 0.f) + b0 : 0.f;
            s0[1] = v0 ? fmaxf(acc[mi][ni][1], 0.f) + b1 : 0.f;
            s1[0] = v1 ? fmaxf(acc[mi][ni][2], 0.f) + b0 : 0.f;
            s1[1] = v1 ? fmaxf(acc[mi][ni][3], 0.f) + b1 : 0.f;
        }
    }
    __syncthreads();

    // --- BN column partial sums --------------------------------------------
    {
        int c  = tid & 127;
        int r0 = (tid >> 7) * 64;
        float s = 0.f, q = 0.f;
#pragma unroll 8
        for (int rr = r0; rr < r0 + 64; rr++) {
            float v = stage[rr * 132 + c];
            s += v;
            q = fmaf(v, v, q);
        }
        atomicAdd(&g_stats[col_off + c], s);
        atomicAdd(&g_stats[256 + col_off + c], q);
    }

    // --- coalesced store ----------------------------------------------------
#pragma unroll
    for (int i = 0; i < 16; i++) {
        int f   = tid + 256 * i;           // float4 index in 128x128 tile
        int row = f >> 5;
        int q   = f & 31;
        int gr  = m0 + row;
        if (gr < N) {
            float4 v = *(float4*)&stage[row * 132 + q * 4];
            *(float4*)&out[(size_t)gr * (2 * DOUT) + col_off + q * 4] = v;
        }
    }
}

// ---------------------------------------------------------------------------
__global__ void bn_finalize_kernel(const float* __restrict__ gamma,
                                   const float* __restrict__ beta,
                                   int N) {
    int c = threadIdx.x;                   // 256 threads
    float inv_n = 1.0f / (float)N;
    float mean = g_stats[c] * inv_n;
    float var  = g_stats[256 + c] * inv_n - mean * mean;
    float s = gamma[c] * rsqrtf(var + BN_EPS);
    g_stats[512 + c] = s;
    g_stats[768 + c] = beta[c] - mean * s;
}

__global__ void bn_apply_kernel(float* __restrict__ out, size_t total4) {
    size_t i = (size_t)blockIdx.x * blockDim.x + threadIdx.x;
    size_t stride = (size_t)gridDim.x * blockDim.x;
    const float4* scale4 = (const float4*)&g_stats[512];
    const float4* shift4 = (const float4*)&g_stats[768];
    for (; i < total4; i += stride) {
        int c4 = (int)(i & 63);            // 64 float4 per 256-col row
        float4 s  = scale4[c4];
        float4 sh = shift4[c4];
        float4 v  = ((float4*)out)[i];
        v.x = fmaf(v.x, s.x, sh.x);
        v.y = fmaf(v.y, s.y, sh.y);
        v.z = fmaf(v.z, s.z, sh.z);
        v.w = fmaf(v.w, s.w, sh.w);
        ((float4*)out)[i] = v;
    }
}

// ---------------------------------------------------------------------------
extern "C" void kernel_launch(void* const* d_in, const int* in_sizes, int n_in,
                              void* d_out, int out_size) {
    const float* feat     = (const float*)d_in[0];
    const float* adj_vals = (const float*)d_in[1];
    const float* W0       = (const float*)d_in[2];
    const float* W1       = (const float*)d_in[3];
    const float* b0       = (const float*)d_in[4];
    const float* b1       = (const float*)d_in[5];
    const float* gamma    = (const float*)d_in[6];
    const float* beta     = (const float*)d_in[7];
    const int*   adj_rows = (const int*)d_in[8];
    const int*   adj_cols = (const int*)d_in[9];
    float* out = (float*)d_out;

    int N = in_sizes[0] / DIN;
    int E = in_sizes[1];

    float* hop1_ptr = nullptr;
    cudaGetSymbolAddress((void**)&hop1_ptr, g_hop1);
    uint32_t* wt_base = nullptr;
    cudaGetSymbolAddress((void**)&wt_base, g_wbf16);

    static bool attr_done = false;
    if (!attr_done) {
        cudaFuncSetAttribute(gemm_mma_kernel,
                             cudaFuncAttributeMaxDynamicSharedMemorySize,
                             GEMM_DYN_SMEM);
        attr_done = true;
    }

    zero_stats_kernel<<<1, 512>>>();
    prep_w_kernel<<<2, 256>>>(W0, W1);
    build_rowptr_kernel<<<(E + 255) / 256, 256>>>(adj_rows, E, N);
    int sblocks = (N * 32 + 255) / 256;
    spmm_kernel<<<sblocks, 256>>>(feat, adj_vals, adj_cols, N);

    int gblocks = (N + 127) / 128;
    gemm_mma_kernel<<<gblocks, 256, GEMM_DYN_SMEM>>>(
        feat, (const uint4*)wt_base, b0, out, N, 0);
    gemm_mma_kernel<<<gblocks, 256, GEMM_DYN_SMEM>>>(
        hop1_ptr, (const uint4*)(wt_base + 16384), b1, out, N, DOUT);

    bn_finalize_kernel<<<1, 256>>>(gamma, beta, N);

    size_t total4 = (size_t)N * (2 * DOUT) / 4;
    int ablocks = (int)((total4 + 255) / 256);
    if (ablocks > 16384) ablocks = 16384;
    bn_apply_kernel<<<ablocks, 256>>>(out, total4);
}

// round 6
// speedup vs baseline: 1.0625x; 1.0625x over previous
#include <cuda_runtime.h>
#include <cuda_bf16.h>
#include <cstdint>

#define DIN   128
#define DOUT  128
#define MAXN  100000
#define BN_EPS 1e-5f

// Scratch (allocation-free rule: __device__ globals)
__device__ float g_hop1[(size_t)MAXN * DIN];   // SpMM result [N,128]
__device__ int   g_rowptr[MAXN + 1];
// [0..255]=colsum, [256..511]=colsumsq, [512..767]=scale, [768..1023]=shift
__device__ float g_stats[1024];

// ---------------------------------------------------------------------------
__global__ void zero_stats_kernel() {
    g_stats[threadIdx.x] = 0.0f;          // 512 threads
}

// adj_rows is sorted; scatter row boundaries into CSR row_ptr.
__global__ void build_rowptr_kernel(const int* __restrict__ rows, int E, int N) {
    int e = blockIdx.x * blockDim.x + threadIdx.x;
    if (e >= E) return;
    int r = rows[e];
    int prev = (e == 0) ? -1 : rows[e - 1];
    for (int rr = prev + 1; rr <= r; rr++) g_rowptr[rr] = e;
    if (e == E - 1) {
        for (int rr = r + 1; rr <= N; rr++) g_rowptr[rr] = E;
    }
}

// One warp per node, lane owns a float4 (4 dims). 8-edge batches with
// predicated loads: all 8 val/col loads then 8 feat gathers issued before
// any FMA -> MLP ~8 per thread (spmm was issue=27%, latency-bound).
__global__ __launch_bounds__(256)
void spmm_kernel(const float* __restrict__ feat,
                 const float* __restrict__ vals,
                 const int*   __restrict__ cols,
                 int N) {
    int warp = (blockIdx.x * blockDim.x + threadIdx.x) >> 5;
    int lane = threadIdx.x & 31;
    if (warp >= N) return;
    int s = g_rowptr[warp];
    int e = g_rowptr[warp + 1];
    float4 acc0 = make_float4(0.f, 0.f, 0.f, 0.f);
    float4 acc1 = make_float4(0.f, 0.f, 0.f, 0.f);

    for (int t = s; t < e; t += 8) {
        float v[8];
        int   c[8];
#pragma unroll
        for (int j = 0; j < 8; j++) {
            int  tj = t + j;
            bool p  = tj < e;
            v[j] = p ? __ldg(&vals[tj]) : 0.f;
            c[j] = p ? __ldg(&cols[tj]) : 0;
        }
        float4 x[8];
#pragma unroll
        for (int j = 0; j < 8; j++) {
            bool p = (t + j) < e;
            x[j] = p ? __ldg(&((const float4*)&feat[(size_t)c[j] * DIN])[lane])
                     : make_float4(0.f, 0.f, 0.f, 0.f);
        }
#pragma unroll
        for (int j = 0; j < 8; j += 2) {
            acc0.x = fmaf(v[j], x[j].x, acc0.x);
            acc0.y = fmaf(v[j], x[j].y, acc0.y);
            acc0.z = fmaf(v[j], x[j].z, acc0.z);
            acc0.w = fmaf(v[j], x[j].w, acc0.w);
            acc1.x = fmaf(v[j + 1], x[j + 1].x, acc1.x);
            acc1.y = fmaf(v[j + 1], x[j + 1].y, acc1.y);
            acc1.z = fmaf(v[j + 1], x[j + 1].z, acc1.z);
            acc1.w = fmaf(v[j + 1], x[j + 1].w, acc1.w);
        }
    }
    acc0.x += acc1.x; acc0.y += acc1.y; acc0.z += acc1.z; acc0.w += acc1.w;
    ((float4*)&g_hop1[(size_t)warp * DIN])[lane] = acc0;
}

// ---------------------------------------------------------------------------
// Packed f32x2 helpers — ptxas never emits FFMA2 from C++; PTX-only path.
__device__ __forceinline__ void ffma2(unsigned long long& d,
                                      unsigned long long a,
                                      unsigned long long b) {
    asm("fma.rn.f32x2 %0, %1, %2, %3;" : "=l"(d) : "l"(a), "l"(b), "l"(d));
}
__device__ __forceinline__ unsigned long long pack2(float x) {
    unsigned long long r;
    unsigned int u = __float_as_uint(x);
    asm("mov.b64 %0, {%1, %1};" : "=l"(r) : "r"(u));
    return r;
}

// Fused GEMM: out[:, col_off..+127] = relu(X @ W) + bias, plus BN stats.
// 128x128 tile, BK=16, 256 threads, 8x8 micro-tile, f32x2-packed FFMA2
// accumulators paired along the row dim (A pairs free from float4 SMEM loads).
#define BM 128
#define BK 16

__global__ __launch_bounds__(256, 2)
void gemm_relu_kernel(const float* __restrict__ X,
                      const float* __restrict__ W,
                      const float* __restrict__ bias,
                      float* __restrict__ out,
                      int N, int col_off) {
    __shared__ float As[BK][BM];    // As[k][m]  (transposed on load)
    __shared__ float Bs[BK][128];   // Bs[k][n]
    __shared__ float red_sum[128];
    __shared__ float red_sq[128];

    int tid = threadIdx.x;
    int tx = tid & 15;              // col group
    int ty = tid >> 4;              // row group
    int m0 = blockIdx.x * BM;

    if (tid < 128) { red_sum[tid] = 0.0f; red_sq[tid] = 0.0f; }

    // acc2[ip][j]: ip=row-pair (i=2*ip, 2*ip+1), j=column 0..7
    unsigned long long acc2[4][8];
#pragma unroll
    for (int ip = 0; ip < 4; ip++)
#pragma unroll
        for (int j = 0; j < 8; j++) acc2[ip][j] = 0ull;

    for (int k0 = 0; k0 < DIN; k0 += BK) {
        // Load A tile (128 rows x 16 k) transposed into As[k][m]
        {
            int row = tid >> 2;             // 0..63
            int kq  = (tid & 3) * 4;        // 0,4,8,12
#pragma unroll
            for (int h = 0; h < 2; h++) {
                int m  = row + h * 64;
                int gr = m0 + m;
                float4 v = make_float4(0.f, 0.f, 0.f, 0.f);
                if (gr < N)
                    v = *(const float4*)&X[(size_t)gr * DIN + k0 + kq];
                As[kq + 0][m] = v.x;
                As[kq + 1][m] = v.y;
                As[kq + 2][m] = v.z;
                As[kq + 3][m] = v.w;
            }
        }
        // Load W tile (16 k x 128 n) straight into Bs[k][n]
        {
            int kr = tid >> 5;              // 0..7
            int c4 = (tid & 31) * 4;
#pragma unroll
            for (int h = 0; h < 2; h++) {
                int k = kr + h * 8;
                *(float4*)&Bs[k][c4] =
                    *(const float4*)&W[(size_t)(k0 + k) * DOUT + c4];
            }
        }
        __syncthreads();

#pragma unroll
        for (int kk = 0; kk < BK; kk++) {
            ulonglong2 alo = *(const ulonglong2*)&As[kk][ty * 4];
            ulonglong2 ahi = *(const ulonglong2*)&As[kk][64 + ty * 4];
            unsigned long long aa[4] = { alo.x, alo.y, ahi.x, ahi.y };
            float4 bl = *(const float4*)&Bs[kk][tx * 4];
            float4 bh = *(const float4*)&Bs[kk][64 + tx * 4];
            unsigned long long b2[8] = {
                pack2(bl.x), pack2(bl.y), pack2(bl.z), pack2(bl.w),
                pack2(bh.x), pack2(bh.y), pack2(bh.z), pack2(bh.w)
            };
#pragma unroll
            for (int ip = 0; ip < 4; ip++)
#pragma unroll
                for (int j = 0; j < 8; j++)
                    ffma2(acc2[ip][j], aa[ip], b2[j]);
        }
        __syncthreads();
    }

    // Epilogue: relu + bias, write out, per-column partial sums
    float bz[8];
#pragma unroll
    for (int j = 0; j < 8; j++) {
        int c = (j < 4) ? tx * 4 + j : 64 + tx * 4 + (j - 4);
        bz[j] = __ldg(&bias[c]);
    }

    float psum[8], psq[8];
#pragma unroll
    for (int j = 0; j < 8; j++) { psum[j] = 0.0f; psq[j] = 0.0f; }

#pragma unroll
    for (int i = 0; i < 8; i++) {
        int ip   = i >> 1;
        int half = i & 1;
        int m  = (i < 4) ? ty * 4 + i : 64 + ty * 4 + (i - 4);
        int gr = m0 + m;
        if (gr >= N) continue;
        float av[8];
#pragma unroll
        for (int j = 0; j < 8; j++) {
            unsigned int lo = (unsigned int)(acc2[ip][j] & 0xFFFFFFFFull);
            unsigned int hi = (unsigned int)(acc2[ip][j] >> 32);
            av[j] = __uint_as_float(half ? hi : lo);
        }
#pragma unroll
        for (int jh = 0; jh < 2; jh++) {
            float r0 = fmaxf(av[jh * 4 + 0], 0.f) + bz[jh * 4 + 0];
            float r1 = fmaxf(av[jh * 4 + 1], 0.f) + bz[jh * 4 + 1];
            float r2 = fmaxf(av[jh * 4 + 2], 0.f) + bz[jh * 4 + 2];
            float r3 = fmaxf(av[jh * 4 + 3], 0.f) + bz[jh * 4 + 3];
            float4 v = make_float4(r0, r1, r2, r3);
            int c0 = (jh == 0) ? tx * 4 : 64 + tx * 4;
            *(float4*)&out[(size_t)gr * (2 * DOUT) + col_off + c0] = v;
            psum[jh * 4 + 0] += r0; psq[jh * 4 + 0] += r0 * r0;
            psum[jh * 4 + 1] += r1; psq[jh * 4 + 1] += r1 * r1;
            psum[jh * 4 + 2] += r2; psq[jh * 4 + 2] += r2 * r2;
            psum[jh * 4 + 3] += r3; psq[jh * 4 + 3] += r3 * r3;
        }
    }
#pragma unroll
    for (int j = 0; j < 8; j++) {
        int c = (j < 4) ? tx * 4 + j : 64 + tx * 4 + (j - 4);
        atomicAdd(&red_sum[c], psum[j]);
        atomicAdd(&red_sq[c],  psq[j]);
    }
    __syncthreads();
    if (tid < 128) {
        atomicAdd(&g_stats[col_off + tid],        red_sum[tid]);
        atomicAdd(&g_stats[256 + col_off + tid],  red_sq[tid]);
    }
}

// ---------------------------------------------------------------------------
__global__ void bn_finalize_kernel(const float* __restrict__ gamma,
                                   const float* __restrict__ beta,
                                   int N) {
    int c = threadIdx.x;                    // 256 threads
    float inv_n = 1.0f / (float)N;
    float mean = g_stats[c] * inv_n;
    float var  = g_stats[256 + c] * inv_n - mean * mean;
    float s = gamma[c] * rsqrtf(var + BN_EPS);
    g_stats[512 + c] = s;
    g_stats[768 + c] = beta[c] - mean * s;
}

__global__ void bn_apply_kernel(float* __restrict__ out, size_t total4) {
    size_t i = (size_t)blockIdx.x * blockDim.x + threadIdx.x;
    size_t stride = (size_t)gridDim.x * blockDim.x;
    const float4* scale4 = (const float4*)&g_stats[512];
    const float4* shift4 = (const float4*)&g_stats[768];
    for (; i < total4; i += stride) {
        int c4 = (int)(i & 63);             // 64 float4 per 256-col row
        float4 s  = scale4[c4];
        float4 sh = shift4[c4];
        float4 v  = ((float4*)out)[i];
        v.x = fmaf(v.x, s.x, sh.x);
        v.y = fmaf(v.y, s.y, sh.y);
        v.z = fmaf(v.z, s.z, sh.z);
        v.w = fmaf(v.w, s.w, sh.w);
        ((float4*)out)[i] = v;
    }
}

// ---------------------------------------------------------------------------
extern "C" void kernel_launch(void* const* d_in, const int* in_sizes, int n_in,
                              void* d_out, int out_size) {
    const float* feat     = (const float*)d_in[0];
    const float* adj_vals = (const float*)d_in[1];
    const float* W0       = (const float*)d_in[2];
    const float* W1       = (const float*)d_in[3];
    const float* b0       = (const float*)d_in[4];
    const float* b1       = (const float*)d_in[5];
    const float* gamma    = (const float*)d_in[6];
    const float* beta     = (const float*)d_in[7];
    const int*   adj_rows = (const int*)d_in[8];
    const int*   adj_cols = (const int*)d_in[9];
    float* out = (float*)d_out;

    int N = in_sizes[0] / DIN;
    int E = in_sizes[1];

    float* hop1_ptr = nullptr;
    cudaGetSymbolAddress((void**)&hop1_ptr, g_hop1);

    // Side stream + events, created once on the eager correctness call
    // (before the harness starts graph capture), reused inside capture via
    // standard event fork/join so gemm0 overlaps rowptr+spmm+gemm1.
    static cudaStream_t s1 = nullptr;
    static cudaEvent_t  eZ = nullptr, eG = nullptr;
    if (s1 == nullptr) {
        cudaStreamCreateWithFlags(&s1, cudaStreamNonBlocking);
        cudaEventCreateWithFlags(&eZ, cudaEventDisableTiming);
        cudaEventCreateWithFlags(&eG, cudaEventDisableTiming);
    }

    int gblocks = (N + BM - 1) / BM;
    int sblocks = (N * 32 + 255) / 256;

    // main (captured/default) stream: zero -> rowptr -> spmm -> gemm1
    zero_stats_kernel<<<1, 512>>>();
    cudaEventRecord(eZ, 0);                         // fork point (stats zeroed)

    // side stream: gemm0 on feat (independent of spmm)
    cudaStreamWaitEvent(s1, eZ, 0);
    gemm_relu_kernel<<<gblocks, 256, 0, s1>>>(feat, W0, b0, out, N, 0);
    cudaEventRecord(eG, s1);

    build_rowptr_kernel<<<(E + 255) / 256, 256>>>(adj_rows, E, N);
    spmm_kernel<<<sblocks, 256>>>(feat, adj_vals, adj_cols, N);
    gemm_relu_kernel<<<gblocks, 256>>>(hop1_ptr, W1, b1, out, N, DOUT);

    // join: BN needs both GEMMs' stats
    cudaStreamWaitEvent(0, eG, 0);
    bn_finalize_kernel<<<1, 256>>>(gamma, beta, N);

    size_t total4 = (size_t)N * (2 * DOUT) / 4;
    int ablocks = (int)((total4 + 255) / 256);
    if (ablocks > 16384) ablocks = 16384;
    bn_apply_kernel<<<ablocks, 256>>>(out, total4);
}